// round 14
// baseline (speedup 1.0000x reference)
#include <cuda_runtime.h>
#include <cstdint>

#define BB 4
#define SS 2048
#define EE 768
#define NHEAD 12
#define HD 64
#define BSROWS (BB*SS)      // 8192
#define QKVN (3*EE)         // 2304

// ---------------- scratch ----------------
__device__ float g_xt[BSROWS*EE];          // tf32-rounded x
__device__ float g_Wp[EE*QKVN];            // packed W_QKV K-major: [e][j], tf32
__device__ float g_Wot[EE*EE];             // tf32-rounded W_O, native [nh][e] (K-major for out)
__device__ float g_q[BB*NHEAD*SS*HD];      // [b,n,s,h]  (tf32-rounded)
__device__ float g_k[BB*NHEAD*SS*HD];
__device__ float g_v[BB*NHEAD*SS*HD];
__device__ float g_z[BB*SS*EE];            // [b,s,n*h] (tf32-rounded)

// ---------------- helpers ----------------
__device__ __forceinline__ uint32_t f2tf(float x) {
    uint32_t u;
    asm("cvt.rna.tf32.f32 %0, %1;" : "=r"(u) : "f"(x));
    return u;
}
__device__ __forceinline__ float f2tff(float x) {
    return __uint_as_float(f2tf(x));
}
__device__ __forceinline__ float4 f2tf4(float4 v) {
    return make_float4(f2tff(v.x), f2tff(v.y), f2tff(v.z), f2tff(v.w));
}
__device__ __forceinline__ void mma8(float* c, const uint32_t* a, uint32_t b0, uint32_t b1) {
    asm volatile(
        "mma.sync.aligned.m16n8k8.row.col.f32.tf32.tf32.f32 "
        "{%0,%1,%2,%3},{%4,%5,%6,%7},{%8,%9},{%0,%1,%2,%3};"
        : "+f"(c[0]), "+f"(c[1]), "+f"(c[2]), "+f"(c[3])
        : "r"(a[0]), "r"(a[1]), "r"(a[2]), "r"(a[3]), "r"(b0), "r"(b1));
}
__device__ __forceinline__ void ldsm4(uint32_t* r, uint32_t saddr) {
    asm volatile(
        "ldmatrix.sync.aligned.m8n8.x4.shared.b16 {%0,%1,%2,%3}, [%4];"
        : "=r"(r[0]), "=r"(r[1]), "=r"(r[2]), "=r"(r[3]) : "r"(saddr));
}
__device__ __forceinline__ uint32_t sptr(const void* p) {
    return (uint32_t)__cvta_generic_to_shared(p);
}
__device__ __forceinline__ void cpa16(uint32_t dst, const void* src) {
    asm volatile("cp.async.cg.shared.global [%0], [%1], 16;" :: "r"(dst), "l"(src));
}
__device__ __forceinline__ void cpa16ca(uint32_t dst, const void* src) {
    asm volatile("cp.async.ca.shared.global [%0], [%1], 16;" :: "r"(dst), "l"(src));
}
__device__ __forceinline__ void cpa_commit() {
    asm volatile("cp.async.commit_group;");
}
template <int N>
__device__ __forceinline__ void cpa_wait() {
    asm volatile("cp.async.wait_group %0;" :: "n"(N));
}

// ---------------- prep kernels ----------------
__global__ void cvt4_kernel(float4* __restrict__ dst, const float4* __restrict__ src, int n4) {
    int i = blockIdx.x * blockDim.x + threadIdx.x;
    if (i < n4) dst[i] = f2tf4(src[i]);
}
// pack W_Q/W_K/W_V -> g_Wp[e][j] (K-major), tf32-rounded
__global__ void packw_kernel(const float* __restrict__ WQ,
                             const float* __restrict__ WK,
                             const float* __restrict__ WV) {
    int idx = blockIdx.x * blockDim.x + threadIdx.x;
    if (idx >= EE * QKVN) return;
    int e   = idx / QKVN;
    int j   = idx - e * QKVN;
    int sel = j / EE;
    int jr  = j - sel * EE;
    int n   = jr >> 6;
    int h   = jr & 63;
    const float* W = (sel == 0) ? WQ : (sel == 1) ? WK : WV;
    g_Wp[idx] = f2tff(W[(n * EE + e) * HD + h]);
}

// ======== GEMM core: BM=128 BN=128 BK=32, 2-stage cp.async, 8 warps 2x4, warp 64x32 ========
// As: [m][k32] pitch 36 (LDSM, 4r mod 32 distinct -> conflict-free).
// Bs: [k32][n] pitch 136 (scalar LDS, bank = 8k+n conflict-free).
#define NSTAGE 2
#define A_STAGE (128*36*4)     // 18432 B
#define B_STAGE (32*136*4)     // 17408 B
#define B_STAGE_F (32*136)
#define GEMM_SMEM (NSTAGE*(A_STAGE + B_STAGE))   // 71680 B

#define GEMM_ISSUE(stg, kk0)                                                        \
    do {                                                                            \
        uint32_t aD = aSt + (stg) * A_STAGE;                                        \
        uint32_t bD = bSt + (stg) * B_STAGE;                                        \
        const float* aS = aG + (kk0);                                               \
        const float* bS = bG + (size_t)(kk0) * LDB;                                 \
        cpa16(aD,      aS);                                                         \
        cpa16(aD + 16, aS + 4);                                                     \
        cpa16(aD + 32, aS + 8);                                                     \
        cpa16(aD + 48, aS + 12);                                                    \
        cpa16ca(bD,      bS);                                                       \
        cpa16ca(bD + 16, bS + 4);                                                   \
        cpa16ca(bD + 32, bS + 8);                                                   \
        cpa16ca(bD + 48, bS + 12);                                                  \
        cpa_commit();                                                               \
    } while (0)

// MODE 0: QKV epilogue (scatter tf32-rounded to g_q/g_k/g_v + bias). MODE 1: out epilogue.
template <int MODE, int LDB>
__device__ __forceinline__ void gemm_body(const float* __restrict__ Amat,
                                          const float* __restrict__ Bmat,
                                          const float* __restrict__ e0,
                                          const float* __restrict__ e1,
                                          const float* __restrict__ e2,
                                          float* __restrict__ Cout) {
    extern __shared__ __align__(128) char gsm[];
    uint32_t smemBase = sptr(gsm);
    uint32_t bsBase = smemBase + NSTAGE * A_STAGE;
    const float* bsF = reinterpret_cast<const float*>(gsm + NSTAGE * A_STAGE);

    int tid = threadIdx.x;
    int wid = tid >> 5, lane = tid & 31;
    int g = lane >> 2, t = lane & 3;
    int warpM = wid >> 2, warpN = wid & 3;
    int rowBlock = blockIdx.y * 128;
    int colBlock = blockIdx.x * 128;

    // A loader: 2 threads/row, 16 floats each (4 x cp.async 16B)
    int aRow = tid >> 1, aK = (tid & 1) * 16;
    const float* aG = Amat + (size_t)(rowBlock + aRow) * EE + aK;
    uint32_t aSt = smemBase + (aRow * 36 + aK) * 4;

    // B loader: 8 threads/row, 16 floats each (coalesced 512B per k-row)
    int bRow = tid >> 3;            // 0..31 (k within stage)
    int bCol = (tid & 7) * 16;      // 0..112 (n)
    const float* bG = Bmat + (size_t)bRow * LDB + colBlock + bCol;
    uint32_t bSt = bsBase + (bRow * 136 + bCol) * 4;

    // A LDSM lane address
    uint32_t aLd = smemBase + ((warpM * 64 + (lane & 15)) * 36 + 4 * (lane >> 4)) * 4;

    float acc[4][4][4];
#pragma unroll
    for (int mt = 0; mt < 4; mt++)
#pragma unroll
        for (int nt = 0; nt < 4; nt++)
#pragma unroll
            for (int i = 0; i < 4; i++) acc[mt][nt][i] = 0.f;

    const int NIT = EE / 32;   // 24
    GEMM_ISSUE(0, 0);

#pragma unroll 1
    for (int it = 0; it < NIT; it++) {
        int buf = it & 1;
        cpa_wait<0>();
        __syncthreads();   // stage it visible + all warps done reading buf^1
        if (it + 1 < NIT) GEMM_ISSUE(buf ^ 1, (it + 1) * 32);
        {
            uint32_t aB = aLd + buf * A_STAGE;
            const float* Bb = bsF + buf * B_STAGE_F + t * 136 + warpN * 32 + g;
#pragma unroll
            for (int ks = 0; ks < 4; ks++) {
                uint32_t af[4][4];
#pragma unroll
                for (int mt = 0; mt < 4; mt++)
                    ldsm4(af[mt], aB + mt * (16 * 36 * 4) + ks * 32);
                const float* Br = Bb + ks * (8 * 136);
                uint32_t bf[4][2];
#pragma unroll
                for (int nt = 0; nt < 4; nt++) {
                    bf[nt][0] = __float_as_uint(Br[nt * 8]);
                    bf[nt][1] = __float_as_uint(Br[nt * 8 + 4 * 136]);
                }
#pragma unroll
                for (int mt = 0; mt < 4; mt++)
#pragma unroll
                    for (int nt = 0; nt < 4; nt++)
                        mma8(acc[mt][nt], af[mt], bf[nt][0], bf[nt][1]);
            }
        }
    }

    if (MODE == 0) {
        int sel = colBlock / EE;
        const float* bias = (sel == 0) ? e0 : (sel == 1) ? e1 : e2;
        float* dst = (sel == 0) ? g_q : (sel == 1) ? g_k : g_v;
#pragma unroll
        for (int mt = 0; mt < 4; mt++) {
#pragma unroll
            for (int nt = 0; nt < 4; nt++) {
                int j  = colBlock + warpN * 32 + nt * 8 + 2 * t;
                int jr = j - sel * EE;
                int n  = jr >> 6;
                int h  = jr & 63;
                float b0 = bias[jr], b1 = bias[jr + 1];
                int r0 = rowBlock + warpM * 64 + mt * 16 + g;
                int r1 = r0 + 8;
                int bb0 = r0 >> 11, s0 = r0 & 2047;
                int bb1 = r1 >> 11, s1 = r1 & 2047;
                *(float2*)(dst + (((size_t)(bb0 * NHEAD + n) * SS) + s0) * HD + h) =
                    make_float2(f2tff(acc[mt][nt][0] + b0), f2tff(acc[mt][nt][1] + b1));
                *(float2*)(dst + (((size_t)(bb1 * NHEAD + n) * SS) + s1) * HD + h) =
                    make_float2(f2tff(acc[mt][nt][2] + b0), f2tff(acc[mt][nt][3] + b1));
            }
        }
    } else {
#pragma unroll
        for (int mt = 0; mt < 4; mt++) {
#pragma unroll
            for (int nt = 0; nt < 4; nt++) {
                int col = colBlock + warpN * 32 + nt * 8 + 2 * t;
                float b0 = e0[col], b1 = e0[col + 1];
                int r0 = rowBlock + warpM * 64 + mt * 16 + g;
                int r1 = r0 + 8;
                *(float2*)(Cout + (size_t)r0 * EE + col) =
                    make_float2(acc[mt][nt][0] + b0, acc[mt][nt][1] + b1);
                *(float2*)(Cout + (size_t)r1 * EE + col) =
                    make_float2(acc[mt][nt][2] + b0, acc[mt][nt][3] + b1);
            }
        }
    }
}

// ---------------- QKV GEMM ----------------
__global__ __launch_bounds__(256, 2) void qkv_gemm_kernel(
    const float* __restrict__ bq, const float* __restrict__ bk,
    const float* __restrict__ bv) {
    gemm_body<0, QKVN>(g_xt, g_Wp, bq, bk, bv, nullptr);
}

// ---------------- output GEMM ----------------
__global__ __launch_bounds__(256, 2) void out_gemm_kernel(
    const float* __restrict__ bo, float* __restrict__ C) {
    gemm_body<1, EE>(g_z, g_Wot, bo, nullptr, nullptr, C);
}

// ---------------- flash attention (cp.async double-buffered K/V, LDSM for K) ----------------
#define KS_PITCH 68
#define VS_PITCH 72
#define KS_SZ (64*KS_PITCH)
#define VS_SZ (64*VS_PITCH)
#define FLASH_SMEM ((2*KS_SZ + 2*VS_SZ)*4)

#define FLASH_ISSUE(dstbuf, kt0)                                                     \
    do {                                                                             \
        int krow0 = (kt0) * 64;                                                      \
        uint32_t kD = kSmem + (dstbuf) * (KS_SZ * 4);                                \
        uint32_t vD = vSmem + (dstbuf) * (VS_SZ * 4);                                \
        _Pragma("unroll")                                                            \
        for (int i = 0; i < 4; i++) {                                                \
            int row = ldRow + i * 16;                                                \
            cpa16ca(kD + (row * KS_PITCH + ldCol) * 4,                               \
                    kb + (size_t)(krow0 + row) * HD + ldCol);                        \
            cpa16ca(vD + (row * VS_PITCH + ldCol) * 4,                               \
                    vb + (size_t)(krow0 + row) * HD + ldCol);                        \
        }                                                                            \
        cpa_commit();                                                                \
    } while (0)

__global__ __launch_bounds__(256, 2) void flash_kernel() {
    extern __shared__ __align__(128) float fsm[];

    int tid = threadIdx.x;
    int wid = tid >> 5, lane = tid & 31;
    int g = lane >> 2, t = lane & 3;
    int bn = blockIdx.y;
    int qt = gridDim.x - 1 - blockIdx.x;
    int q0 = qt * 128;

    const float* qb = g_q + (size_t)bn * SS * HD;
    const float* kb = g_k + (size_t)bn * SS * HD;
    const float* vb = g_v + (size_t)bn * SS * HD;

    int ldRow = tid >> 4;
    int ldCol = (tid & 15) * 4;

    uint32_t kSmem = sptr(fsm);
    uint32_t vSmem = kSmem + 2 * KS_SZ * 4;
    uint32_t kLdBase = kSmem + ((lane & 7) * KS_PITCH + 4 * (lane >> 3)) * 4;

    int qrow = q0 + wid * 16;
    uint32_t qf[8][4];
#pragma unroll
    for (int ks = 0; ks < 8; ks++) {
        qf[ks][0] = f2tf(0.125f * qb[(size_t)(qrow + g) * HD + ks * 8 + t]);
        qf[ks][1] = f2tf(0.125f * qb[(size_t)(qrow + g + 8) * HD + ks * 8 + t]);
        qf[ks][2] = f2tf(0.125f * qb[(size_t)(qrow + g) * HD + ks * 8 + t + 4]);
        qf[ks][3] = f2tf(0.125f * qb[(size_t)(qrow + g + 8) * HD + ks * 8 + t + 4]);
    }

    float acc[8][4];
#pragma unroll
    for (int nt = 0; nt < 8; nt++)
#pragma unroll
        for (int i = 0; i < 4; i++) acc[nt][i] = 0.f;
    float m0 = -1e30f, m1 = -1e30f, l0 = 0.f, l1 = 0.f;

    int ntk = 2 * qt + 2;
    int r0 = qrow + g, r1 = qrow + g + 8;

    FLASH_ISSUE(0, 0);

#pragma unroll 1
    for (int kt = 0; kt < ntk; kt++) {
        int buf = kt & 1;
        uint32_t kLd = kLdBase + buf * (KS_SZ * 4);
        const float* Vb = fsm + 2 * KS_SZ + buf * VS_SZ;
        int k0 = kt * 64;
        bool more = (kt + 1) < ntk;

        cpa_wait<0>();
        __syncthreads();
        if (more) FLASH_ISSUE(buf ^ 1, kt + 1);

        // S = Q K^T
        float sc[8][4];
#pragma unroll
        for (int nt = 0; nt < 8; nt++)
#pragma unroll
            for (int i = 0; i < 4; i++) sc[nt][i] = 0.f;
#pragma unroll
        for (int nt = 0; nt < 8; nt++) {
            uint32_t rowAddr = kLd + nt * (8 * KS_PITCH * 4);
#pragma unroll
            for (int ksp = 0; ksp < 4; ksp++) {
                uint32_t kf[4];
                ldsm4(kf, rowAddr + ksp * 64);
                mma8(sc[nt], qf[2 * ksp],     kf[0], kf[1]);
                mma8(sc[nt], qf[2 * ksp + 1], kf[2], kf[3]);
            }
        }

        if (kt >= 2 * qt) {
#pragma unroll
            for (int nt = 0; nt < 8; nt++) {
                int cA = k0 + nt * 8 + 2 * t;
                int cB = cA + 1;
                if (cA > r0) sc[nt][0] = -1e30f;
                if (cB > r0) sc[nt][1] = -1e30f;
                if (cA > r1) sc[nt][2] = -1e30f;
                if (cB > r1) sc[nt][3] = -1e30f;
            }
        }

        float rm0 = -1e30f, rm1 = -1e30f;
#pragma unroll
        for (int nt = 0; nt < 8; nt++) {
            rm0 = fmaxf(rm0, fmaxf(sc[nt][0], sc[nt][1]));
            rm1 = fmaxf(rm1, fmaxf(sc[nt][2], sc[nt][3]));
        }
        rm0 = fmaxf(rm0, __shfl_xor_sync(0xffffffffu, rm0, 1));
        rm0 = fmaxf(rm0, __shfl_xor_sync(0xffffffffu, rm0, 2));
        rm1 = fmaxf(rm1, __shfl_xor_sync(0xffffffffu, rm1, 1));
        rm1 = fmaxf(rm1, __shfl_xor_sync(0xffffffffu, rm1, 2));
        float mn0 = fmaxf(m0, rm0), mn1 = fmaxf(m1, rm1);
        float al0 = __expf(m0 - mn0), al1 = __expf(m1 - mn1);
        m0 = mn0; m1 = mn1;

        float rs0 = 0.f, rs1 = 0.f;
#pragma unroll
        for (int nt = 0; nt < 8; nt++) {
            sc[nt][0] = __expf(sc[nt][0] - m0); rs0 += sc[nt][0];
            sc[nt][1] = __expf(sc[nt][1] - m0); rs0 += sc[nt][1];
            sc[nt][2] = __expf(sc[nt][2] - m1); rs1 += sc[nt][2];
            sc[nt][3] = __expf(sc[nt][3] - m1); rs1 += sc[nt][3];
        }
        rs0 += __shfl_xor_sync(0xffffffffu, rs0, 1);
        rs0 += __shfl_xor_sync(0xffffffffu, rs0, 2);
        rs1 += __shfl_xor_sync(0xffffffffu, rs1, 1);
        rs1 += __shfl_xor_sync(0xffffffffu, rs1, 2);
        l0 = l0 * al0 + rs0;
        l1 = l1 * al1 + rs1;
#pragma unroll
        for (int nt = 0; nt < 8; nt++) {
            acc[nt][0] *= al0; acc[nt][1] *= al0;
            acc[nt][2] *= al1; acc[nt][3] *= al1;
        }

        int src  = g * 4 + (t >> 1);
        int src2 = src + 2;
#pragma unroll
        for (int j = 0; j < 8; j++) {
            float x0 = __shfl_sync(0xffffffffu, sc[j][0], src);
            float x1 = __shfl_sync(0xffffffffu, sc[j][1], src);
            float y0 = __shfl_sync(0xffffffffu, sc[j][0], src2);
            float y1 = __shfl_sync(0xffffffffu, sc[j][1], src2);
            float z0 = __shfl_sync(0xffffffffu, sc[j][2], src);
            float z1 = __shfl_sync(0xffffffffu, sc[j][3], src);
            float w0 = __shfl_sync(0xffffffffu, sc[j][2], src2);
            float w1 = __shfl_sync(0xffffffffu, sc[j][3], src2);
            uint32_t pa[4];
            pa[0] = f2tf((t & 1) ? x1 : x0);
            pa[1] = f2tf((t & 1) ? z1 : z0);
            pa[2] = f2tf((t & 1) ? y1 : y0);
            pa[3] = f2tf((t & 1) ? w1 : w0);
#pragma unroll
            for (int hd = 0; hd < 8; hd++) {
                uint32_t b0 = __float_as_uint(Vb[(j * 8 + t) * VS_PITCH + hd * 8 + g]);
                uint32_t b1 = __float_as_uint(Vb[(j * 8 + t + 4) * VS_PITCH + hd * 8 + g]);
                mma8(acc[hd], pa, b0, b1);
            }
        }
    }

    int b_ = bn / NHEAD;
    int n_ = bn - b_ * NHEAD;
    float inv0 = 1.f / l0, inv1 = 1.f / l1;
#pragma unroll
    for (int hd = 0; hd < 8; hd++) {
        int h = hd * 8 + 2 * t;
        *(float2*)(g_z + ((size_t)(b_ * SS + r0) * NHEAD + n_) * HD + h) =
            make_float2(f2tff(acc[hd][0] * inv0), f2tff(acc[hd][1] * inv0));
        *(float2*)(g_z + ((size_t)(b_ * SS + r1) * NHEAD + n_) * HD + h) =
            make_float2(f2tff(acc[hd][2] * inv1), f2tff(acc[hd][3] * inv1));
    }
}

// ---------------- launch ----------------
extern "C" void kernel_launch(void* const* d_in, const int* in_sizes, int n_in,
                              void* d_out, int out_size) {
    const float* x  = (const float*)d_in[0];
    const float* WQ = (const float*)d_in[1];
    const float* WK = (const float*)d_in[2];
    const float* WV = (const float*)d_in[3];
    const float* WO = (const float*)d_in[4];
    const float* bq = (const float*)d_in[5];
    const float* bk = (const float*)d_in[6];
    const float* bv = (const float*)d_in[7];
    const float* bo = (const float*)d_in[8];
    float* out = (float*)d_out;

    static int inited = 0;
    if (!inited) {
        cudaFuncSetAttribute(flash_kernel,
                             cudaFuncAttributeMaxDynamicSharedMemorySize, FLASH_SMEM);
        cudaFuncSetAttribute(qkv_gemm_kernel,
                             cudaFuncAttributeMaxDynamicSharedMemorySize, GEMM_SMEM);
        cudaFuncSetAttribute(out_gemm_kernel,
                             cudaFuncAttributeMaxDynamicSharedMemorySize, GEMM_SMEM);
        inited = 1;
    }

    float* xt;  cudaGetSymbolAddress((void**)&xt,  g_xt);
    float* wot; cudaGetSymbolAddress((void**)&wot, g_Wot);

    cvt4_kernel<<<(BSROWS * EE / 4 + 255) / 256, 256>>>((float4*)xt, (const float4*)x,
                                                        BSROWS * EE / 4);
    packw_kernel<<<(EE * QKVN + 255) / 256, 256>>>(WQ, WK, WV);
    cvt4_kernel<<<(EE * EE / 4 + 255) / 256, 256>>>((float4*)wot, (const float4*)WO,
                                                    EE * EE / 4);
    qkv_gemm_kernel<<<dim3(QKVN / 128, BSROWS / 128), 256, GEMM_SMEM>>>(bq, bk, bv);
    flash_kernel<<<dim3(SS / 128, BB * NHEAD), 256, FLASH_SMEM>>>();
    out_gemm_kernel<<<dim3(EE / 128, BSROWS / 128), 256, GEMM_SMEM>>>(bo, out);
}

// round 15
// speedup vs baseline: 1.0618x; 1.0618x over previous
#include <cuda_runtime.h>
#include <cstdint>

#define BB 4
#define SS 2048
#define EE 768
#define NHEAD 12
#define HD 64
#define BSROWS (BB*SS)      // 8192
#define QKVN (3*EE)         // 2304

// ---------------- scratch ----------------
__device__ float g_xt[BSROWS*EE];          // tf32-rounded x
__device__ float g_Wp[EE*QKVN];            // packed W_QKV K-major: [e][j], tf32
__device__ float g_Wot[EE*EE];             // tf32-rounded W_O, native [nh][e]
__device__ float g_q[BB*NHEAD*SS*HD];      // [b,n,s,h]  (tf32-rounded)
__device__ float g_k[BB*NHEAD*SS*HD];
__device__ float g_v[BB*NHEAD*SS*HD];
__device__ float g_z[BB*SS*EE];            // [b,s,n*h] (tf32-rounded)

// ---------------- helpers ----------------
__device__ __forceinline__ uint32_t f2tf(float x) {
    uint32_t u;
    asm("cvt.rna.tf32.f32 %0, %1;" : "=r"(u) : "f"(x));
    return u;
}
__device__ __forceinline__ float f2tff(float x) {
    return __uint_as_float(f2tf(x));
}
__device__ __forceinline__ float4 f2tf4(float4 v) {
    return make_float4(f2tff(v.x), f2tff(v.y), f2tff(v.z), f2tff(v.w));
}
__device__ __forceinline__ void mma8(float* c, const uint32_t* a, uint32_t b0, uint32_t b1) {
    asm volatile(
        "mma.sync.aligned.m16n8k8.row.col.f32.tf32.tf32.f32 "
        "{%0,%1,%2,%3},{%4,%5,%6,%7},{%8,%9},{%0,%1,%2,%3};"
        : "+f"(c[0]), "+f"(c[1]), "+f"(c[2]), "+f"(c[3])
        : "r"(a[0]), "r"(a[1]), "r"(a[2]), "r"(a[3]), "r"(b0), "r"(b1));
}
__device__ __forceinline__ void ldsm4(uint32_t* r, uint32_t saddr) {
    asm volatile(
        "ldmatrix.sync.aligned.m8n8.x4.shared.b16 {%0,%1,%2,%3}, [%4];"
        : "=r"(r[0]), "=r"(r[1]), "=r"(r[2]), "=r"(r[3]) : "r"(saddr));
}
__device__ __forceinline__ uint32_t sptr(const void* p) {
    return (uint32_t)__cvta_generic_to_shared(p);
}
__device__ __forceinline__ void cpa16(uint32_t dst, const void* src) {
    asm volatile("cp.async.cg.shared.global [%0], [%1], 16;" :: "r"(dst), "l"(src));
}
__device__ __forceinline__ void cpa16ca(uint32_t dst, const void* src) {
    asm volatile("cp.async.ca.shared.global [%0], [%1], 16;" :: "r"(dst), "l"(src));
}
__device__ __forceinline__ void cpa_commit() {
    asm volatile("cp.async.commit_group;");
}
template <int N>
__device__ __forceinline__ void cpa_wait() {
    asm volatile("cp.async.wait_group %0;" :: "n"(N));
}

// ---------------- prep kernels ----------------
__global__ void cvt4_kernel(float4* __restrict__ dst, const float4* __restrict__ src, int n4) {
    int i = blockIdx.x * blockDim.x + threadIdx.x;
    if (i < n4) dst[i] = f2tf4(src[i]);
}
// pack W_Q/W_K/W_V -> g_Wp[e][j] (K-major), tf32-rounded
__global__ void packw_kernel(const float* __restrict__ WQ,
                             const float* __restrict__ WK,
                             const float* __restrict__ WV) {
    int idx = blockIdx.x * blockDim.x + threadIdx.x;
    if (idx >= EE * QKVN) return;
    int e   = idx / QKVN;
    int j   = idx - e * QKVN;
    int sel = j / EE;
    int jr  = j - sel * EE;
    int n   = jr >> 6;
    int h   = jr & 63;
    const float* W = (sel == 0) ? WQ : (sel == 1) ? WK : WV;
    g_Wp[idx] = f2tff(W[(n * EE + e) * HD + h]);
}

// ======== GEMM core (R12 config): BM=128 BN=128 BK=16, 4-stage cp.async ========
// As: [m][k] pitch 20 (LDSM).  Bs: [k][n] pitch 136 (scalar LDS, bank=8k+n conflict-free).
#define NSTAGE 4
#define A_STAGE (128*20*4)     // 10240 B
#define B_STAGE (16*136*4)     // 8704 B
#define B_STAGE_F (16*136)
#define GEMM_SMEM (NSTAGE*(A_STAGE + B_STAGE))   // 75776 B

#define GEMM_ISSUE(stg, kk0)                                                        \
    do {                                                                            \
        uint32_t aD = aSt + (stg) * A_STAGE;                                        \
        uint32_t bD = bSt + (stg) * B_STAGE;                                        \
        const float* aS = aG + (kk0);                                               \
        const float* bS = bG + (size_t)(kk0) * LDB;                                 \
        cpa16(aD, aS);                                                              \
        cpa16(aD + 16, aS + 4);                                                     \
        cpa16ca(bD, bS);                                                            \
        cpa16ca(bD + 16, bS + 4);                                                   \
        cpa_commit();                                                               \
    } while (0)

// MODE 0: QKV epilogue (scatter tf32-rounded to g_q/g_k/g_v + bias). MODE 1: out epilogue.
template <int MODE, int LDB>
__device__ __forceinline__ void gemm_body(const float* __restrict__ Amat,
                                          const float* __restrict__ Bmat,
                                          const float* __restrict__ e0,
                                          const float* __restrict__ e1,
                                          const float* __restrict__ e2,
                                          float* __restrict__ Cout) {
    extern __shared__ __align__(128) char gsm[];
    uint32_t smemBase = sptr(gsm);
    uint32_t bsBase = smemBase + NSTAGE * A_STAGE;
    const float* bsF = reinterpret_cast<const float*>(gsm + NSTAGE * A_STAGE);

    int tid = threadIdx.x;
    int wid = tid >> 5, lane = tid & 31;
    int g = lane >> 2, t = lane & 3;
    int warpM = wid >> 2, warpN = wid & 3;
    int rowBlock = blockIdx.y * 128;
    int colBlock = blockIdx.x * 128;

    // A loader (cp.async, coalesced)
    int aRow = tid >> 1, aK = (tid & 1) * 8;
    const float* aG = Amat + (size_t)(rowBlock + aRow) * EE + aK;
    uint32_t aSt = smemBase + (aRow * 20 + aK) * 4;

    // B loader (cp.async, coalesced: 16 k-rows x 512B contiguous)
    int bRow = tid >> 4;            // 0..15 (k within stage)
    int bCol = (tid & 15) * 8;      // 0..120 (n)
    const float* bG = Bmat + (size_t)bRow * LDB + colBlock + bCol;
    uint32_t bSt = bsBase + (bRow * 136 + bCol) * 4;

    // A LDSM lane address
    uint32_t aLd = smemBase + ((warpM * 64 + (lane & 15)) * 20 + 4 * (lane >> 4)) * 4;

    float acc[4][4][4];
#pragma unroll
    for (int mt = 0; mt < 4; mt++)
#pragma unroll
        for (int nt = 0; nt < 4; nt++)
#pragma unroll
            for (int i = 0; i < 4; i++) acc[mt][nt][i] = 0.f;

    const int NIT = EE / 16;   // 48
    GEMM_ISSUE(0, 0);
    GEMM_ISSUE(1, 16);
    GEMM_ISSUE(2, 32);

#pragma unroll 1
    for (int it = 0; it < NIT; it++) {
        int buf = it & (NSTAGE - 1);
        cpa_wait<2>();
        __syncthreads();
        if (it + 3 < NIT) {
            int nstg = (it + 3) & (NSTAGE - 1);
            GEMM_ISSUE(nstg, (it + 3) * 16);
        }
        {
            uint32_t aB = aLd + buf * A_STAGE;
            const float* Bb = bsF + buf * B_STAGE_F + t * 136 + warpN * 32 + g;
#pragma unroll
            for (int ks = 0; ks < 2; ks++) {
                uint32_t af[4][4];
#pragma unroll
                for (int mt = 0; mt < 4; mt++)
                    ldsm4(af[mt], aB + mt * (16 * 20 * 4) + ks * 32);
                const float* Br = Bb + ks * (8 * 136);
                uint32_t bf[4][2];
#pragma unroll
                for (int nt = 0; nt < 4; nt++) {
                    bf[nt][0] = __float_as_uint(Br[nt * 8]);
                    bf[nt][1] = __float_as_uint(Br[nt * 8 + 4 * 136]);
                }
#pragma unroll
                for (int mt = 0; mt < 4; mt++)
#pragma unroll
                    for (int nt = 0; nt < 4; nt++)
                        mma8(acc[mt][nt], af[mt], bf[nt][0], bf[nt][1]);
            }
        }
    }

    if (MODE == 0) {
        int sel = colBlock / EE;
        const float* bias = (sel == 0) ? e0 : (sel == 1) ? e1 : e2;
        float* dst = (sel == 0) ? g_q : (sel == 1) ? g_k : g_v;
#pragma unroll
        for (int mt = 0; mt < 4; mt++) {
#pragma unroll
            for (int nt = 0; nt < 4; nt++) {
                int j  = colBlock + warpN * 32 + nt * 8 + 2 * t;
                int jr = j - sel * EE;
                int n  = jr >> 6;
                int h  = jr & 63;
                float b0 = bias[jr], b1 = bias[jr + 1];
                int r0 = rowBlock + warpM * 64 + mt * 16 + g;
                int r1 = r0 + 8;
                int bb0 = r0 >> 11, s0 = r0 & 2047;
                int bb1 = r1 >> 11, s1 = r1 & 2047;
                *(float2*)(dst + (((size_t)(bb0 * NHEAD + n) * SS) + s0) * HD + h) =
                    make_float2(f2tff(acc[mt][nt][0] + b0), f2tff(acc[mt][nt][1] + b1));
                *(float2*)(dst + (((size_t)(bb1 * NHEAD + n) * SS) + s1) * HD + h) =
                    make_float2(f2tff(acc[mt][nt][2] + b0), f2tff(acc[mt][nt][3] + b1));
            }
        }
    } else {
#pragma unroll
        for (int mt = 0; mt < 4; mt++) {
#pragma unroll
            for (int nt = 0; nt < 4; nt++) {
                int col = colBlock + warpN * 32 + nt * 8 + 2 * t;
                float b0 = e0[col], b1 = e0[col + 1];
                int r0 = rowBlock + warpM * 64 + mt * 16 + g;
                int r1 = r0 + 8;
                *(float2*)(Cout + (size_t)r0 * EE + col) =
                    make_float2(acc[mt][nt][0] + b0, acc[mt][nt][1] + b1);
                *(float2*)(Cout + (size_t)r1 * EE + col) =
                    make_float2(acc[mt][nt][2] + b0, acc[mt][nt][3] + b1);
            }
        }
    }
}

// ---------------- QKV GEMM ----------------
__global__ __launch_bounds__(256, 2) void qkv_gemm_kernel(
    const float* __restrict__ bq, const float* __restrict__ bk,
    const float* __restrict__ bv) {
    gemm_body<0, QKVN>(g_xt, g_Wp, bq, bk, bv, nullptr);
}

// ---------------- output GEMM ----------------
__global__ __launch_bounds__(256, 2) void out_gemm_kernel(
    const float* __restrict__ bo, float* __restrict__ C) {
    gemm_body<1, EE>(g_z, g_Wot, bo, nullptr, nullptr, C);
}

// ---------------- flash attention (register-prefetch double-buffered K/V, LDSM K) ----------------
// inputs pre-rounded to tf32 -> raw copies, no cvt in the loop
#define KS_PITCH 68
#define VS_PITCH 72
#define KS_SZ (64*KS_PITCH)
#define VS_SZ (64*VS_PITCH)
#define FLASH_SMEM ((2*KS_SZ + 2*VS_SZ)*4)

__global__ __launch_bounds__(256, 1) void flash_kernel() {
    extern __shared__ __align__(128) float fsm[];

    int tid = threadIdx.x;
    int wid = tid >> 5, lane = tid & 31;
    int g = lane >> 2, t = lane & 3;
    int bn = blockIdx.y;
    int qt = gridDim.x - 1 - blockIdx.x;   // heavy blocks first
    int q0 = qt * 128;

    const float* qb = g_q + (size_t)bn * SS * HD;
    const float* kb = g_k + (size_t)bn * SS * HD;
    const float* vb = g_v + (size_t)bn * SS * HD;

    int ldRow = tid >> 4;
    int ldCol = (tid & 15) * 4;

    uint32_t kLdBase = sptr(fsm) + ((lane & 7) * KS_PITCH + 4 * (lane >> 3)) * 4;

    // Q fragments: pre-rounded, 0.125x is exact (exponent shift) -> still tf32
    int qrow = q0 + wid * 16;
    uint32_t qf[8][4];
#pragma unroll
    for (int ks = 0; ks < 8; ks++) {
        qf[ks][0] = __float_as_uint(0.125f * qb[(size_t)(qrow + g) * HD + ks * 8 + t]);
        qf[ks][1] = __float_as_uint(0.125f * qb[(size_t)(qrow + g + 8) * HD + ks * 8 + t]);
        qf[ks][2] = __float_as_uint(0.125f * qb[(size_t)(qrow + g) * HD + ks * 8 + t + 4]);
        qf[ks][3] = __float_as_uint(0.125f * qb[(size_t)(qrow + g + 8) * HD + ks * 8 + t + 4]);
    }

    float acc[8][4];
#pragma unroll
    for (int nt = 0; nt < 8; nt++)
#pragma unroll
        for (int i = 0; i < 4; i++) acc[nt][i] = 0.f;
    float m0 = -1e30f, m1 = -1e30f, l0 = 0.f, l1 = 0.f;

    int ntk = 2 * qt + 2;
    int r0 = qrow + g, r1 = qrow + g + 8;

    // prologue: tile 0 -> buffer 0 (raw)
    float4 rk[4], rv[4];
#pragma unroll
    for (int i = 0; i < 4; i++) {
        int row = ldRow + i * 16;
        rk[i] = *(const float4*)(kb + (size_t)row * HD + ldCol);
        rv[i] = *(const float4*)(vb + (size_t)row * HD + ldCol);
    }
#pragma unroll
    for (int i = 0; i < 4; i++) {
        int row = ldRow + i * 16;
        *(float4*)&fsm[row * KS_PITCH + ldCol] = rk[i];
        *(float4*)&fsm[2 * KS_SZ + row * VS_PITCH + ldCol] = rv[i];
    }
    __syncthreads();

#pragma unroll 1
    for (int kt = 0; kt < ntk; kt++) {
        int buf = kt & 1;
        uint32_t kLd = kLdBase + buf * (KS_SZ * 4);
        const float* Vb = fsm + 2 * KS_SZ + buf * VS_SZ;
        int k0 = kt * 64;
        bool more = (kt + 1) < ntk;

        // S = Q K^T
        float sc[8][4];
#pragma unroll
        for (int nt = 0; nt < 8; nt++)
#pragma unroll
            for (int i = 0; i < 4; i++) sc[nt][i] = 0.f;
#pragma unroll
        for (int nt = 0; nt < 8; nt++) {
            uint32_t rowAddr = kLd + nt * (8 * KS_PITCH * 4);
#pragma unroll
            for (int ksp = 0; ksp < 4; ksp++) {
                uint32_t kf[4];
                ldsm4(kf, rowAddr + ksp * 64);
                mma8(sc[nt], qf[2 * ksp],     kf[0], kf[1]);
                mma8(sc[nt], qf[2 * ksp + 1], kf[2], kf[3]);
            }
        }

        // causal mask (diagonal region tiles only)
        if (kt >= 2 * qt) {
#pragma unroll
            for (int nt = 0; nt < 8; nt++) {
                int cA = k0 + nt * 8 + 2 * t;
                int cB = cA + 1;
                if (cA > r0) sc[nt][0] = -1e30f;
                if (cB > r0) sc[nt][1] = -1e30f;
                if (cA > r1) sc[nt][2] = -1e30f;
                if (cB > r1) sc[nt][3] = -1e30f;
            }
        }

        // online softmax (quad reductions)
        float rm0 = -1e30f, rm1 = -1e30f;
#pragma unroll
        for (int nt = 0; nt < 8; nt++) {
            rm0 = fmaxf(rm0, fmaxf(sc[nt][0], sc[nt][1]));
            rm1 = fmaxf(rm1, fmaxf(sc[nt][2], sc[nt][3]));
        }
        rm0 = fmaxf(rm0, __shfl_xor_sync(0xffffffffu, rm0, 1));
        rm0 = fmaxf(rm0, __shfl_xor_sync(0xffffffffu, rm0, 2));
        rm1 = fmaxf(rm1, __shfl_xor_sync(0xffffffffu, rm1, 1));
        rm1 = fmaxf(rm1, __shfl_xor_sync(0xffffffffu, rm1, 2));
        float mn0 = fmaxf(m0, rm0), mn1 = fmaxf(m1, rm1);
        float al0 = __expf(m0 - mn0), al1 = __expf(m1 - mn1);
        m0 = mn0; m1 = mn1;

        float rs0 = 0.f, rs1 = 0.f;
#pragma unroll
        for (int nt = 0; nt < 8; nt++) {
            sc[nt][0] = __expf(sc[nt][0] - m0); rs0 += sc[nt][0];
            sc[nt][1] = __expf(sc[nt][1] - m0); rs0 += sc[nt][1];
            sc[nt][2] = __expf(sc[nt][2] - m1); rs1 += sc[nt][2];
            sc[nt][3] = __expf(sc[nt][3] - m1); rs1 += sc[nt][3];
        }
        rs0 += __shfl_xor_sync(0xffffffffu, rs0, 1);
        rs0 += __shfl_xor_sync(0xffffffffu, rs0, 2);
        rs1 += __shfl_xor_sync(0xffffffffu, rs1, 1);
        rs1 += __shfl_xor_sync(0xffffffffu, rs1, 2);
        l0 = l0 * al0 + rs0;
        l1 = l1 * al1 + rs1;
#pragma unroll
        for (int nt = 0; nt < 8; nt++) {
            acc[nt][0] *= al0; acc[nt][1] *= al0;
            acc[nt][2] *= al1; acc[nt][3] *= al1;
        }

        // prefetch next K/V tile into registers (hide gmem latency under PV)
        if (more) {
            int nk0 = k0 + 64;
#pragma unroll
            for (int i = 0; i < 4; i++) {
                int row = nk0 + ldRow + i * 16;
                rk[i] = *(const float4*)(kb + (size_t)row * HD + ldCol);
                rv[i] = *(const float4*)(vb + (size_t)row * HD + ldCol);
            }
        }

        // O += P @ V  (C-frag -> A-frag transpose via quad shuffles)
        int src  = g * 4 + (t >> 1);
        int src2 = src + 2;
#pragma unroll
        for (int j = 0; j < 8; j++) {
            float x0 = __shfl_sync(0xffffffffu, sc[j][0], src);
            float x1 = __shfl_sync(0xffffffffu, sc[j][1], src);
            float y0 = __shfl_sync(0xffffffffu, sc[j][0], src2);
            float y1 = __shfl_sync(0xffffffffu, sc[j][1], src2);
            float z0 = __shfl_sync(0xffffffffu, sc[j][2], src);
            float z1 = __shfl_sync(0xffffffffu, sc[j][3], src);
            float w0 = __shfl_sync(0xffffffffu, sc[j][2], src2);
            float w1 = __shfl_sync(0xffffffffu, sc[j][3], src2);
            uint32_t pa[4];
            pa[0] = f2tf((t & 1) ? x1 : x0);
            pa[1] = f2tf((t & 1) ? z1 : z0);
            pa[2] = f2tf((t & 1) ? y1 : y0);
            pa[3] = f2tf((t & 1) ? w1 : w0);
#pragma unroll
            for (int hd = 0; hd < 8; hd++) {
                uint32_t b0 = __float_as_uint(Vb[(j * 8 + t) * VS_PITCH + hd * 8 + g]);
                uint32_t b1 = __float_as_uint(Vb[(j * 8 + t + 4) * VS_PITCH + hd * 8 + g]);
                mma8(acc[hd], pa, b0, b1);
            }
        }

        // store prefetched tile into the other buffer (raw)
        if (more) {
            float* Kn = fsm + (buf ^ 1) * KS_SZ;
            float* Vn = fsm + 2 * KS_SZ + (buf ^ 1) * VS_SZ;
#pragma unroll
            for (int i = 0; i < 4; i++) {
                int row = ldRow + i * 16;
                *(float4*)&Kn[row * KS_PITCH + ldCol] = rk[i];
                *(float4*)&Vn[row * VS_PITCH + ldCol] = rv[i];
            }
        }
        __syncthreads();
    }

    // epilogue -> g_z (tf32-rounded for out_gemm's cp.async path)
    int b_ = bn / NHEAD;
    int n_ = bn - b_ * NHEAD;
    float inv0 = 1.f / l0, inv1 = 1.f / l1;
#pragma unroll
    for (int hd = 0; hd < 8; hd++) {
        int h = hd * 8 + 2 * t;
        *(float2*)(g_z + ((size_t)(b_ * SS + r0) * NHEAD + n_) * HD + h) =
            make_float2(f2tff(acc[hd][0] * inv0), f2tff(acc[hd][1] * inv0));
        *(float2*)(g_z + ((size_t)(b_ * SS + r1) * NHEAD + n_) * HD + h) =
            make_float2(f2tff(acc[hd][2] * inv1), f2tff(acc[hd][3] * inv1));
    }
}

// ---------------- launch ----------------
extern "C" void kernel_launch(void* const* d_in, const int* in_sizes, int n_in,
                              void* d_out, int out_size) {
    const float* x  = (const float*)d_in[0];
    const float* WQ = (const float*)d_in[1];
    const float* WK = (const float*)d_in[2];
    const float* WV = (const float*)d_in[3];
    const float* WO = (const float*)d_in[4];
    const float* bq = (const float*)d_in[5];
    const float* bk = (const float*)d_in[6];
    const float* bv = (const float*)d_in[7];
    const float* bo = (const float*)d_in[8];
    float* out = (float*)d_out;

    static int inited = 0;
    if (!inited) {
        cudaFuncSetAttribute(flash_kernel,
                             cudaFuncAttributeMaxDynamicSharedMemorySize, FLASH_SMEM);
        cudaFuncSetAttribute(qkv_gemm_kernel,
                             cudaFuncAttributeMaxDynamicSharedMemorySize, GEMM_SMEM);
        cudaFuncSetAttribute(out_gemm_kernel,
                             cudaFuncAttributeMaxDynamicSharedMemorySize, GEMM_SMEM);
        inited = 1;
    }

    float* xt;  cudaGetSymbolAddress((void**)&xt,  g_xt);
    float* wot; cudaGetSymbolAddress((void**)&wot, g_Wot);

    cvt4_kernel<<<(BSROWS * EE / 4 + 255) / 256, 256>>>((float4*)xt, (const float4*)x,
                                                        BSROWS * EE / 4);
    packw_kernel<<<(EE * QKVN + 255) / 256, 256>>>(WQ, WK, WV);
    cvt4_kernel<<<(EE * EE / 4 + 255) / 256, 256>>>((float4*)wot, (const float4*)WO,
                                                    EE * EE / 4);
    qkv_gemm_kernel<<<dim3(QKVN / 128, BSROWS / 128), 256, GEMM_SMEM>>>(bq, bk, bv);
    flash_kernel<<<dim3(SS / 128, BB * NHEAD), 256, FLASH_SMEM>>>();
    out_gemm_kernel<<<dim3(EE / 128, BSROWS / 128), 256, GEMM_SMEM>>>(bo, out);
}

// round 17
// speedup vs baseline: 1.0791x; 1.0162x over previous
#include <cuda_runtime.h>
#include <cstdint>

#define BB 4
#define SS 2048
#define EE 768
#define NHEAD 12
#define HD 64
#define BSROWS (BB*SS)      // 8192
#define QKVN (3*EE)         // 2304

// ---------------- scratch ----------------
__device__ float g_xt[BSROWS*EE];          // tf32(rna)-rounded x
__device__ float g_Wp[EE*QKVN];            // packed W_QKV K-major: [e][j], tf32 (rna)
__device__ float g_Wot[EE*EE];             // tf32(rna)-rounded W_O, native [nh][e]
__device__ float g_q[BB*NHEAD*SS*HD];      // [b,n,s,h]  (tf32-rounded)
__device__ float g_k[BB*NHEAD*SS*HD];
__device__ float g_v[BB*NHEAD*SS*HD];
__device__ float g_z[BB*SS*EE];            // [b,s,n*h] (tf32-rounded)

// ---------------- helpers ----------------
__device__ __forceinline__ uint32_t f2tf(float x) {
    uint32_t u;
    asm("cvt.rna.tf32.f32 %0, %1;" : "=r"(u) : "f"(x));
    return u;
}
__device__ __forceinline__ float f2tff(float x) {
    return __uint_as_float(f2tf(x));
}
__device__ __forceinline__ float4 f2tf4(float4 v) {
    return make_float4(f2tff(v.x), f2tff(v.y), f2tff(v.z), f2tff(v.w));
}
__device__ __forceinline__ void mma8(float* c, const uint32_t* a, uint32_t b0, uint32_t b1) {
    asm volatile(
        "mma.sync.aligned.m16n8k8.row.col.f32.tf32.tf32.f32 "
        "{%0,%1,%2,%3},{%4,%5,%6,%7},{%8,%9},{%0,%1,%2,%3};"
        : "+f"(c[0]), "+f"(c[1]), "+f"(c[2]), "+f"(c[3])
        : "r"(a[0]), "r"(a[1]), "r"(a[2]), "r"(a[3]), "r"(b0), "r"(b1));
}
__device__ __forceinline__ void ldsm4(uint32_t* r, uint32_t saddr) {
    asm volatile(
        "ldmatrix.sync.aligned.m8n8.x4.shared.b16 {%0,%1,%2,%3}, [%4];"
        : "=r"(r[0]), "=r"(r[1]), "=r"(r[2]), "=r"(r[3]) : "r"(saddr));
}
__device__ __forceinline__ uint32_t sptr(const void* p) {
    return (uint32_t)__cvta_generic_to_shared(p);
}
__device__ __forceinline__ void cpa16(uint32_t dst, const void* src) {
    asm volatile("cp.async.cg.shared.global [%0], [%1], 16;" :: "r"(dst), "l"(src));
}
__device__ __forceinline__ void cpa16ca(uint32_t dst, const void* src) {
    asm volatile("cp.async.ca.shared.global [%0], [%1], 16;" :: "r"(dst), "l"(src));
}
__device__ __forceinline__ void cpa_commit() {
    asm volatile("cp.async.commit_group;");
}
template <int N>
__device__ __forceinline__ void cpa_wait() {
    asm volatile("cp.async.wait_group %0;" :: "n"(N));
}

// ---------------- prep kernels ----------------
__global__ void cvt4_kernel(float4* __restrict__ dst, const float4* __restrict__ src, int n4) {
    int i = blockIdx.x * blockDim.x + threadIdx.x;
    if (i < n4) dst[i] = f2tf4(src[i]);
}
// pack W_Q/W_K/W_V -> g_Wp[e][j] (K-major), rna-rounded
__global__ void packw_kernel(const float* __restrict__ WQ,
                             const float* __restrict__ WK,
                             const float* __restrict__ WV) {
    int idx = blockIdx.x * blockDim.x + threadIdx.x;
    if (idx >= EE * QKVN) return;
    int e   = idx / QKVN;
    int j   = idx - e * QKVN;
    int sel = j / EE;
    int jr  = j - sel * EE;
    int n   = jr >> 6;
    int h   = jr & 63;
    const float* W = (sel == 0) ? WQ : (sel == 1) ? WK : WV;
    g_Wp[idx] = f2tff(W[(n * EE + e) * HD + h]);
}

// ======== GEMM core: BM=128 BN=128 BK=16, 5-stage cp.async, 8 warps 2x4, warp 64x32 ========
// As: [m][k] pitch 20 (LDSM).  Bs: [k][n] pitch 136 (scalar LDS, bank=8k+n conflict-free).
#define NSTAGE 5
#define A_STAGE (128*20*4)     // 10240 B
#define B_STAGE (16*136*4)     // 8704 B
#define B_STAGE_F (16*136)
#define GEMM_SMEM (NSTAGE*(A_STAGE + B_STAGE))   // 94720 B

#define GEMM_ISSUE(stg, kk0)                                                        \
    do {                                                                            \
        uint32_t aD = aSt + (stg) * A_STAGE;                                        \
        uint32_t bD = bSt + (stg) * B_STAGE;                                        \
        const float* aS = aG + (kk0);                                               \
        const float* bS = bG + (size_t)(kk0) * LDB;                                 \
        cpa16(aD, aS);                                                              \
        cpa16(aD + 16, aS + 4);                                                     \
        cpa16ca(bD, bS);                                                            \
        cpa16ca(bD + 16, bS + 4);                                                   \
        cpa_commit();                                                               \
    } while (0)

// MODE 0: QKV epilogue (scatter tf32-rounded to g_q/g_k/g_v + bias). MODE 1: out epilogue.
template <int MODE, int LDB>
__device__ __forceinline__ void gemm_body(const float* __restrict__ Amat,
                                          const float* __restrict__ Bmat,
                                          const float* __restrict__ e0,
                                          const float* __restrict__ e1,
                                          const float* __restrict__ e2,
                                          float* __restrict__ Cout) {
    extern __shared__ __align__(128) char gsm[];
    uint32_t smemBase = sptr(gsm);
    uint32_t bsBase = smemBase + NSTAGE * A_STAGE;
    const float* bsF = reinterpret_cast<const float*>(gsm + NSTAGE * A_STAGE);

    int tid = threadIdx.x;
    int wid = tid >> 5, lane = tid & 31;
    int g = lane >> 2, t = lane & 3;
    int warpM = wid >> 2, warpN = wid & 3;
    int rowBlock = blockIdx.y * 128;
    int colBlock = blockIdx.x * 128;

    // A loader (cp.async, coalesced)
    int aRow = tid >> 1, aK = (tid & 1) * 8;
    const float* aG = Amat + (size_t)(rowBlock + aRow) * EE + aK;
    uint32_t aSt = smemBase + (aRow * 20 + aK) * 4;

    // B loader (cp.async, coalesced: 16 k-rows x 512B contiguous)
    int bRow = tid >> 4;            // 0..15 (k within stage)
    int bCol = (tid & 15) * 8;      // 0..120 (n)
    const float* bG = Bmat + (size_t)bRow * LDB + colBlock + bCol;
    uint32_t bSt = bsBase + (bRow * 136 + bCol) * 4;

    // A LDSM lane address
    uint32_t aLd = smemBase + ((warpM * 64 + (lane & 15)) * 20 + 4 * (lane >> 4)) * 4;

    float acc[4][4][4];
#pragma unroll
    for (int mt = 0; mt < 4; mt++)
#pragma unroll
        for (int nt = 0; nt < 4; nt++)
#pragma unroll
            for (int i = 0; i < 4; i++) acc[mt][nt][i] = 0.f;

    const int NIT = EE / 16;   // 48
    GEMM_ISSUE(0, 0);
    GEMM_ISSUE(1, 16);
    GEMM_ISSUE(2, 32);
    GEMM_ISSUE(3, 48);

#pragma unroll 1
    for (int it = 0; it < NIT; it++) {
        int buf = it % NSTAGE;
        cpa_wait<3>();
        __syncthreads();
        if (it + 4 < NIT) {
            int nstg = (it + 4) % NSTAGE;
            GEMM_ISSUE(nstg, (it + 4) * 16);
        }
        {
            uint32_t aB = aLd + buf * A_STAGE;
            const float* Bb = bsF + buf * B_STAGE_F + t * 136 + warpN * 32 + g;
#pragma unroll
            for (int ks = 0; ks < 2; ks++) {
                uint32_t af[4][4];
#pragma unroll
                for (int mt = 0; mt < 4; mt++)
                    ldsm4(af[mt], aB + mt * (16 * 20 * 4) + ks * 32);
                const float* Br = Bb + ks * (8 * 136);
                uint32_t bf[4][2];
#pragma unroll
                for (int nt = 0; nt < 4; nt++) {
                    bf[nt][0] = __float_as_uint(Br[nt * 8]);
                    bf[nt][1] = __float_as_uint(Br[nt * 8 + 4 * 136]);
                }
#pragma unroll
                for (int mt = 0; mt < 4; mt++)
#pragma unroll
                    for (int nt = 0; nt < 4; nt++)
                        mma8(acc[mt][nt], af[mt], bf[nt][0], bf[nt][1]);
            }
        }
    }

    if (MODE == 0) {
        int sel = colBlock / EE;
        const float* bias = (sel == 0) ? e0 : (sel == 1) ? e1 : e2;
        float* dst = (sel == 0) ? g_q : (sel == 1) ? g_k : g_v;
#pragma unroll
        for (int mt = 0; mt < 4; mt++) {
#pragma unroll
            for (int nt = 0; nt < 4; nt++) {
                int j  = colBlock + warpN * 32 + nt * 8 + 2 * t;
                int jr = j - sel * EE;
                int n  = jr >> 6;
                int h  = jr & 63;
                float b0 = bias[jr], b1 = bias[jr + 1];
                int r0 = rowBlock + warpM * 64 + mt * 16 + g;
                int r1 = r0 + 8;
                int bb0 = r0 >> 11, s0 = r0 & 2047;
                int bb1 = r1 >> 11, s1 = r1 & 2047;
                *(float2*)(dst + (((size_t)(bb0 * NHEAD + n) * SS) + s0) * HD + h) =
                    make_float2(f2tff(acc[mt][nt][0] + b0), f2tff(acc[mt][nt][1] + b1));
                *(float2*)(dst + (((size_t)(bb1 * NHEAD + n) * SS) + s1) * HD + h) =
                    make_float2(f2tff(acc[mt][nt][2] + b0), f2tff(acc[mt][nt][3] + b1));
            }
        }
    } else {
#pragma unroll
        for (int mt = 0; mt < 4; mt++) {
#pragma unroll
            for (int nt = 0; nt < 4; nt++) {
                int col = colBlock + warpN * 32 + nt * 8 + 2 * t;
                float b0 = e0[col], b1 = e0[col + 1];
                int r0 = rowBlock + warpM * 64 + mt * 16 + g;
                int r1 = r0 + 8;
                *(float2*)(Cout + (size_t)r0 * EE + col) =
                    make_float2(acc[mt][nt][0] + b0, acc[mt][nt][1] + b1);
                *(float2*)(Cout + (size_t)r1 * EE + col) =
                    make_float2(acc[mt][nt][2] + b0, acc[mt][nt][3] + b1);
            }
        }
    }
}

// ---------------- QKV GEMM ----------------
__global__ __launch_bounds__(256, 2) void qkv_gemm_kernel(
    const float* __restrict__ bq, const float* __restrict__ bk,
    const float* __restrict__ bv) {
    gemm_body<0, QKVN>(g_xt, g_Wp, bq, bk, bv, nullptr);
}

// ---------------- output GEMM ----------------
__global__ __launch_bounds__(256, 2) void out_gemm_kernel(
    const float* __restrict__ bo, float* __restrict__ C) {
    gemm_body<1, EE>(g_z, g_Wot, bo, nullptr, nullptr, C);
}

// ---------------- flash attention (cp.async double-buffered K/V, LDSM for K) ----------------
#define KS_PITCH 68
#define VS_PITCH 72
#define KS_SZ (64*KS_PITCH)
#define VS_SZ (64*VS_PITCH)
#define FLASH_SMEM ((2*KS_SZ + 2*VS_SZ)*4)

#define FLASH_ISSUE(dstbuf, kt0)                                                     \
    do {                                                                             \
        int krow0 = (kt0) * 64;                                                      \
        uint32_t kD = kSmem + (dstbuf) * (KS_SZ * 4);                                \
        uint32_t vD = vSmem + (dstbuf) * (VS_SZ * 4);                                \
        _Pragma("unroll")                                                            \
        for (int i = 0; i < 4; i++) {                                                \
            int row = ldRow + i * 16;                                                \
            cpa16ca(kD + (row * KS_PITCH + ldCol) * 4,                               \
                    kb + (size_t)(krow0 + row) * HD + ldCol);                        \
            cpa16ca(vD + (row * VS_PITCH + ldCol) * 4,                               \
                    vb + (size_t)(krow0 + row) * HD + ldCol);                        \
        }                                                                            \
        cpa_commit();                                                                \
    } while (0)

__global__ __launch_bounds__(256, 2) void flash_kernel() {
    extern __shared__ __align__(128) float fsm[];

    int tid = threadIdx.x;
    int wid = tid >> 5, lane = tid & 31;
    int g = lane >> 2, t = lane & 3;
    int bn = blockIdx.y;
    int qt = gridDim.x - 1 - blockIdx.x;
    int q0 = qt * 128;

    const float* qb = g_q + (size_t)bn * SS * HD;
    const float* kb = g_k + (size_t)bn * SS * HD;
    const float* vb = g_v + (size_t)bn * SS * HD;

    int ldRow = tid >> 4;
    int ldCol = (tid & 15) * 4;

    uint32_t kSmem = sptr(fsm);
    uint32_t vSmem = kSmem + 2 * KS_SZ * 4;
    uint32_t kLdBase = kSmem + ((lane & 7) * KS_PITCH + 4 * (lane >> 3)) * 4;

    // Q pre-rounded; 0.125x exact (exponent shift) -> still tf32
    int qrow = q0 + wid * 16;
    uint32_t qf[8][4];
#pragma unroll
    for (int ks = 0; ks < 8; ks++) {
        qf[ks][0] = __float_as_uint(0.125f * qb[(size_t)(qrow + g) * HD + ks * 8 + t]);
        qf[ks][1] = __float_as_uint(0.125f * qb[(size_t)(qrow + g + 8) * HD + ks * 8 + t]);
        qf[ks][2] = __float_as_uint(0.125f * qb[(size_t)(qrow + g) * HD + ks * 8 + t + 4]);
        qf[ks][3] = __float_as_uint(0.125f * qb[(size_t)(qrow + g + 8) * HD + ks * 8 + t + 4]);
    }

    float acc[8][4];
#pragma unroll
    for (int nt = 0; nt < 8; nt++)
#pragma unroll
        for (int i = 0; i < 4; i++) acc[nt][i] = 0.f;
    float m0 = -1e30f, m1 = -1e30f, l0 = 0.f, l1 = 0.f;

    int ntk = 2 * qt + 2;
    int r0 = qrow + g, r1 = qrow + g + 8;

    FLASH_ISSUE(0, 0);

#pragma unroll 1
    for (int kt = 0; kt < ntk; kt++) {
        int buf = kt & 1;
        uint32_t kLd = kLdBase + buf * (KS_SZ * 4);
        const float* Vb = fsm + 2 * KS_SZ + buf * VS_SZ;
        int k0 = kt * 64;
        bool more = (kt + 1) < ntk;

        cpa_wait<0>();
        __syncthreads();
        if (more) FLASH_ISSUE(buf ^ 1, kt + 1);

        // S = Q K^T
        float sc[8][4];
#pragma unroll
        for (int nt = 0; nt < 8; nt++)
#pragma unroll
            for (int i = 0; i < 4; i++) sc[nt][i] = 0.f;
#pragma unroll
        for (int nt = 0; nt < 8; nt++) {
            uint32_t rowAddr = kLd + nt * (8 * KS_PITCH * 4);
#pragma unroll
            for (int ksp = 0; ksp < 4; ksp++) {
                uint32_t kf[4];
                ldsm4(kf, rowAddr + ksp * 64);
                mma8(sc[nt], qf[2 * ksp],     kf[0], kf[1]);
                mma8(sc[nt], qf[2 * ksp + 1], kf[2], kf[3]);
            }
        }

        if (kt >= 2 * qt) {
#pragma unroll
            for (int nt = 0; nt < 8; nt++) {
                int cA = k0 + nt * 8 + 2 * t;
                int cB = cA + 1;
                if (cA > r0) sc[nt][0] = -1e30f;
                if (cB > r0) sc[nt][1] = -1e30f;
                if (cA > r1) sc[nt][2] = -1e30f;
                if (cB > r1) sc[nt][3] = -1e30f;
            }
        }

        float rm0 = -1e30f, rm1 = -1e30f;
#pragma unroll
        for (int nt = 0; nt < 8; nt++) {
            rm0 = fmaxf(rm0, fmaxf(sc[nt][0], sc[nt][1]));
            rm1 = fmaxf(rm1, fmaxf(sc[nt][2], sc[nt][3]));
        }
        rm0 = fmaxf(rm0, __shfl_xor_sync(0xffffffffu, rm0, 1));
        rm0 = fmaxf(rm0, __shfl_xor_sync(0xffffffffu, rm0, 2));
        rm1 = fmaxf(rm1, __shfl_xor_sync(0xffffffffu, rm1, 1));
        rm1 = fmaxf(rm1, __shfl_xor_sync(0xffffffffu, rm1, 2));
        float mn0 = fmaxf(m0, rm0), mn1 = fmaxf(m1, rm1);
        float al0 = __expf(m0 - mn0), al1 = __expf(m1 - mn1);
        m0 = mn0; m1 = mn1;

        float rs0 = 0.f, rs1 = 0.f;
#pragma unroll
        for (int nt = 0; nt < 8; nt++) {
            sc[nt][0] = __expf(sc[nt][0] - m0); rs0 += sc[nt][0];
            sc[nt][1] = __expf(sc[nt][1] - m0); rs0 += sc[nt][1];
            sc[nt][2] = __expf(sc[nt][2] - m1); rs1 += sc[nt][2];
            sc[nt][3] = __expf(sc[nt][3] - m1); rs1 += sc[nt][3];
        }
        rs0 += __shfl_xor_sync(0xffffffffu, rs0, 1);
        rs0 += __shfl_xor_sync(0xffffffffu, rs0, 2);
        rs1 += __shfl_xor_sync(0xffffffffu, rs1, 1);
        rs1 += __shfl_xor_sync(0xffffffffu, rs1, 2);
        l0 = l0 * al0 + rs0;
        l1 = l1 * al1 + rs1;
#pragma unroll
        for (int nt = 0; nt < 8; nt++) {
            acc[nt][0] *= al0; acc[nt][1] *= al0;
            acc[nt][2] *= al1; acc[nt][3] *= al1;
        }

        // O += P @ V  (C-frag -> A-frag transpose via quad shuffles; P fed raw: ~6e-5 err)
        int src  = g * 4 + (t >> 1);
        int src2 = src + 2;
#pragma unroll
        for (int j = 0; j < 8; j++) {
            float x0 = __shfl_sync(0xffffffffu, sc[j][0], src);
            float x1 = __shfl_sync(0xffffffffu, sc[j][1], src);
            float y0 = __shfl_sync(0xffffffffu, sc[j][0], src2);
            float y1 = __shfl_sync(0xffffffffu, sc[j][1], src2);
            float z0 = __shfl_sync(0xffffffffu, sc[j][2], src);
            float z1 = __shfl_sync(0xffffffffu, sc[j][3], src);
            float w0 = __shfl_sync(0xffffffffu, sc[j][2], src2);
            float w1 = __shfl_sync(0xffffffffu, sc[j][3], src2);
            uint32_t pa[4];
            pa[0] = __float_as_uint((t & 1) ? x1 : x0);
            pa[1] = __float_as_uint((t & 1) ? z1 : z0);
            pa[2] = __float_as_uint((t & 1) ? y1 : y0);
            pa[3] = __float_as_uint((t & 1) ? w1 : w0);
#pragma unroll
            for (int hd = 0; hd < 8; hd++) {
                uint32_t b0 = __float_as_uint(Vb[(j * 8 + t) * VS_PITCH + hd * 8 + g]);
                uint32_t b1 = __float_as_uint(Vb[(j * 8 + t + 4) * VS_PITCH + hd * 8 + g]);
                mma8(acc[hd], pa, b0, b1);
            }
        }
    }

    int b_ = bn / NHEAD;
    int n_ = bn - b_ * NHEAD;
    float inv0 = 1.f / l0, inv1 = 1.f / l1;
#pragma unroll
    for (int hd = 0; hd < 8; hd++) {
        int h = hd * 8 + 2 * t;
        *(float2*)(g_z + ((size_t)(b_ * SS + r0) * NHEAD + n_) * HD + h) =
            make_float2(f2tff(acc[hd][0] * inv0), f2tff(acc[hd][1] * inv0));
        *(float2*)(g_z + ((size_t)(b_ * SS + r1) * NHEAD + n_) * HD + h) =
            make_float2(f2tff(acc[hd][2] * inv1), f2tff(acc[hd][3] * inv1));
    }
}

// ---------------- launch ----------------
extern "C" void kernel_launch(void* const* d_in, const int* in_sizes, int n_in,
                              void* d_out, int out_size) {
    const float* x  = (const float*)d_in[0];
    const float* WQ = (const float*)d_in[1];
    const float* WK = (const float*)d_in[2];
    const float* WV = (const float*)d_in[3];
    const float* WO = (const float*)d_in[4];
    const float* bq = (const float*)d_in[5];
    const float* bk = (const float*)d_in[6];
    const float* bv = (const float*)d_in[7];
    const float* bo = (const float*)d_in[8];
    float* out = (float*)d_out;

    static int inited = 0;
    if (!inited) {
        cudaFuncSetAttribute(flash_kernel,
                             cudaFuncAttributeMaxDynamicSharedMemorySize, FLASH_SMEM);
        cudaFuncSetAttribute(qkv_gemm_kernel,
                             cudaFuncAttributeMaxDynamicSharedMemorySize, GEMM_SMEM);
        cudaFuncSetAttribute(out_gemm_kernel,
                             cudaFuncAttributeMaxDynamicSharedMemorySize, GEMM_SMEM);
        inited = 1;
    }

    float* xt;  cudaGetSymbolAddress((void**)&xt,  g_xt);
    float* wot; cudaGetSymbolAddress((void**)&wot, g_Wot);

    cvt4_kernel<<<(BSROWS * EE / 4 + 255) / 256, 256>>>((float4*)xt, (const float4*)x,
                                                        BSROWS * EE / 4);
    packw_kernel<<<(EE * QKVN + 255) / 256, 256>>>(WQ, WK, WV);
    cvt4_kernel<<<(EE * EE / 4 + 255) / 256, 256>>>((float4*)wot, (const float4*)WO,
                                                    EE * EE / 4);
    qkv_gemm_kernel<<<dim3(QKVN / 128, BSROWS / 128), 256, GEMM_SMEM>>>(bq, bk, bv);
    flash_kernel<<<dim3(SS / 128, BB * NHEAD), 256, FLASH_SMEM>>>();
    out_gemm_kernel<<<dim3(EE / 128, BSROWS / 128), 256, GEMM_SMEM>>>(bo, out);
}